// round 1
// baseline (speedup 1.0000x reference)
#include <cuda_runtime.h>
#include <cuda_bf16.h>
#include <cstdint>

// ---------------- problem constants ----------------
#define NN     50000      // nodes
#define FDIM   128        // features (in == hid)
#define EMAX   600000     // max edges

// ---------------- device scratch (no allocations allowed) ----------------
__device__ float g_t[(size_t)NN * FDIM];     // GEMM output (pre-aggregation)
__device__ float g_h[(size_t)NN * FDIM];     // layer activations
__device__ int   g_cnt[NN];                  // edge-count histogram (per dst)
__device__ int   g_cnt2[NN];                 // scatter cursors
__device__ int   g_rowptr[NN + 1];           // CSR row pointers (by dst)
__device__ int   g_bsums[64];                // scan block sums
__device__ float g_dinv[NN];                 // deg^{-1/2}
__device__ int   g_esrc[EMAX];               // sorted-by-dst source ids
__device__ float g_enorm[EMAX];              // per-edge norm = dinv[s]*dinv[d]

// ---------------- setup kernels ----------------
__global__ void k_zero_counts(int n) {
    int i = blockIdx.x * blockDim.x + threadIdx.x;
    if (i < n) { g_cnt[i] = 0; g_cnt2[i] = 0; }
}

__global__ void k_count(const int* __restrict__ ei, int E) {
    int e = blockIdx.x * blockDim.x + threadIdx.x;
    if (e < E) atomicAdd(&g_cnt[ei[E + e]], 1);   // dst = row 1
}

__global__ void k_dinv(int n) {
    int i = blockIdx.x * blockDim.x + threadIdx.x;
    if (i < n) g_dinv[i] = rsqrtf((float)(g_cnt[i] + 1));   // +1 self loop
}

// block-level exclusive scan of g_cnt into g_rowptr (partial), block sums out
__global__ void k_scan1(int n) {
    __shared__ int s[1024];
    int i = blockIdx.x * 1024 + threadIdx.x;
    int v = (i < n) ? g_cnt[i] : 0;
    s[threadIdx.x] = v;
    __syncthreads();
    for (int off = 1; off < 1024; off <<= 1) {
        int t = (threadIdx.x >= off) ? s[threadIdx.x - off] : 0;
        __syncthreads();
        s[threadIdx.x] += t;
        __syncthreads();
    }
    if (i < n) g_rowptr[i] = s[threadIdx.x] - v;       // exclusive
    if (threadIdx.x == 1023) g_bsums[blockIdx.x] = s[1023];
}

__global__ void k_scan2(int nb) {
    // single thread: nb <= 49
    int run = 0;
    for (int i = 0; i < nb; i++) { int v = g_bsums[i]; g_bsums[i] = run; run += v; }
}

__global__ void k_scan3(int n, int E) {
    int i = blockIdx.x * 1024 + threadIdx.x;
    if (i < n) g_rowptr[i] += g_bsums[blockIdx.x];
    if (i == 0) g_rowptr[n] = E;
}

__global__ void k_scatter(const int* __restrict__ ei, int E) {
    int e = blockIdx.x * blockDim.x + threadIdx.x;
    if (e >= E) return;
    int s = ei[e];
    int d = ei[E + e];
    int pos = g_rowptr[d] + atomicAdd(&g_cnt2[d], 1);
    g_esrc[pos]  = s;
    g_enorm[pos] = g_dinv[s] * g_dinv[d];
}

// ---------------- GEMM: C[nrows,128] = A[nrows,128] @ W[128,128] ----------------
// Block: 256 threads, 128-row tile, full K=128 and N=128 in smem.
// Each thread: 8x8 register microtile.
#define XS_PITCH 129
__global__ __launch_bounds__(256) void k_gemm128(const float* __restrict__ A,
                                                 const float* __restrict__ W,
                                                 float* __restrict__ C, int nrows) {
    extern __shared__ float sm[];
    float* Xs = sm;                       // [128][129]
    float* Ws = sm + 128 * XS_PITCH;      // [128][128]
    const int tid  = threadIdx.x;
    const int row0 = blockIdx.x * 128;

    // load W (16384 floats) as float4
    for (int i = tid; i < 128 * 128 / 4; i += 256)
        ((float4*)Ws)[i] = ((const float4*)W)[i];

    // load X tile (row-major, padded pitch)
    for (int i = tid; i < 128 * 128 / 4; i += 256) {
        int idx = i * 4;
        int r = idx >> 7, k = idx & 127;
        float4 v = make_float4(0.f, 0.f, 0.f, 0.f);
        if (row0 + r < nrows)
            v = ((const float4*)A)[(size_t)(row0 + r) * 32 + (k >> 2)];
        float* p = Xs + r * XS_PITCH + k;
        p[0] = v.x; p[1] = v.y; p[2] = v.z; p[3] = v.w;
    }
    __syncthreads();

    const int tx = tid & 15, ty = tid >> 4;
    const int r0 = ty * 8, c0 = tx * 8;

    float acc[8][8];
#pragma unroll
    for (int i = 0; i < 8; i++)
#pragma unroll
        for (int j = 0; j < 8; j++) acc[i][j] = 0.f;

#pragma unroll 4
    for (int k = 0; k < 128; k++) {
        float4 w0 = *(const float4*)(Ws + k * 128 + c0);
        float4 w1 = *(const float4*)(Ws + k * 128 + c0 + 4);
        float wv[8] = {w0.x, w0.y, w0.z, w0.w, w1.x, w1.y, w1.z, w1.w};
        float xv[8];
#pragma unroll
        for (int i = 0; i < 8; i++) xv[i] = Xs[(r0 + i) * XS_PITCH + k];
#pragma unroll
        for (int i = 0; i < 8; i++)
#pragma unroll
            for (int j = 0; j < 8; j++) acc[i][j] = fmaf(xv[i], wv[j], acc[i][j]);
    }

#pragma unroll
    for (int i = 0; i < 8; i++) {
        int r = row0 + r0 + i;
        if (r < nrows) {
            float4 o0 = make_float4(acc[i][0], acc[i][1], acc[i][2], acc[i][3]);
            float4 o1 = make_float4(acc[i][4], acc[i][5], acc[i][6], acc[i][7]);
            *(float4*)(C + (size_t)r * 128 + c0)     = o0;
            *(float4*)(C + (size_t)r * 128 + c0 + 4) = o1;
        }
    }
}

// ---------------- aggregation: out[n] = b + dinv[n]^2*H[n] + sum_e norm*H[src] ----------------
// one warp per node; lane handles a float4 of the 128-wide feature row
__global__ __launch_bounds__(128) void k_aggregate(const float* __restrict__ H,
                                                   const float* __restrict__ bias,
                                                   float* __restrict__ out,
                                                   int n, int relu) {
    int warp = threadIdx.x >> 5;
    int lane = threadIdx.x & 31;
    int node = blockIdx.x * 4 + warp;
    if (node >= n) return;

    float di = g_dinv[node];
    float di2 = di * di;
    float4 self = *(const float4*)(H + (size_t)node * 128 + lane * 4);
    float4 a0 = make_float4(self.x * di2, self.y * di2, self.z * di2, self.w * di2);
    float4 a1 = make_float4(0.f, 0.f, 0.f, 0.f);

    int e0 = g_rowptr[node], e1 = g_rowptr[node + 1];
    int e = e0;
    for (; e + 1 < e1; e += 2) {
        int   s0 = g_esrc[e],     s1 = g_esrc[e + 1];
        float m0 = g_enorm[e],    m1 = g_enorm[e + 1];
        float4 h0 = *(const float4*)(H + (size_t)s0 * 128 + lane * 4);
        float4 h1 = *(const float4*)(H + (size_t)s1 * 128 + lane * 4);
        a0.x = fmaf(h0.x, m0, a0.x); a0.y = fmaf(h0.y, m0, a0.y);
        a0.z = fmaf(h0.z, m0, a0.z); a0.w = fmaf(h0.w, m0, a0.w);
        a1.x = fmaf(h1.x, m1, a1.x); a1.y = fmaf(h1.y, m1, a1.y);
        a1.z = fmaf(h1.z, m1, a1.z); a1.w = fmaf(h1.w, m1, a1.w);
    }
    if (e < e1) {
        int   s0 = g_esrc[e];
        float m0 = g_enorm[e];
        float4 h0 = *(const float4*)(H + (size_t)s0 * 128 + lane * 4);
        a0.x = fmaf(h0.x, m0, a0.x); a0.y = fmaf(h0.y, m0, a0.y);
        a0.z = fmaf(h0.z, m0, a0.z); a0.w = fmaf(h0.w, m0, a0.w);
    }

    float4 b = *(const float4*)(bias + lane * 4);
    float4 o = make_float4(a0.x + a1.x + b.x, a0.y + a1.y + b.y,
                           a0.z + a1.z + b.z, a0.w + a1.w + b.w);
    if (relu) {
        o.x = fmaxf(o.x, 0.f); o.y = fmaxf(o.y, 0.f);
        o.z = fmaxf(o.z, 0.f); o.w = fmaxf(o.w, 0.f);
    }
    *(float4*)(out + (size_t)node * 128 + lane * 4) = o;
}

__global__ void k_dup(const float* __restrict__ src, float* __restrict__ dst, int n) {
    int i = blockIdx.x * blockDim.x + threadIdx.x;
    if (i < n) dst[i] = src[i];
}

// ---------------- launch ----------------
extern "C" void kernel_launch(void* const* d_in, const int* in_sizes, int n_in,
                              void* d_out, int out_size) {
    const float* x  = (const float*)d_in[0];
    const int*   ei = (const int*)d_in[1];
    const float* W1 = (const float*)d_in[2];
    const float* b1 = (const float*)d_in[3];
    const float* W2 = (const float*)d_in[4];
    const float* b2 = (const float*)d_in[5];
    const float* W3 = (const float*)d_in[6];
    const float* b3 = (const float*)d_in[7];

    int N = in_sizes[0] / FDIM;
    if (N > NN) N = NN;
    int E = in_sizes[1] / 2;
    if (E > EMAX) E = EMAX;

    // resolve scratch symbols (host-side API, not a stream op)
    static float* t = nullptr;
    static float* h = nullptr;
    static bool inited = false;
    if (!inited) {
        cudaGetSymbolAddress((void**)&t, g_t);
        cudaGetSymbolAddress((void**)&h, g_h);
        cudaFuncSetAttribute(k_gemm128, cudaFuncAttributeMaxDynamicSharedMemorySize,
                             (128 * XS_PITCH + 128 * 128) * sizeof(float));
        inited = true;
    }

    const int smem = (128 * XS_PITCH + 128 * 128) * sizeof(float);
    const int nScan = (N + 1023) / 1024;

    // --- build normalization + CSR (deterministic, every call) ---
    k_zero_counts<<<(N + 255) / 256, 256>>>(N);
    k_count<<<(E + 255) / 256, 256>>>(ei, E);
    k_dinv<<<(N + 255) / 256, 256>>>(N);
    k_scan1<<<nScan, 1024>>>(N);
    k_scan2<<<1, 1>>>(nScan);
    k_scan3<<<nScan, 1024>>>(N, E);
    k_scatter<<<(E + 255) / 256, 256>>>(ei, E);

    const int gGemm = (N + 127) / 128;
    const int gAgg  = (N + 3) / 4;

    // layer 1: h = relu(Agg(x @ W1) + b1)
    k_gemm128<<<gGemm, 256, smem>>>(x, W1, t, N);
    k_aggregate<<<gAgg, 128>>>(t, b1, h, N, 1);
    // layer 2
    k_gemm128<<<gGemm, 256, smem>>>(h, W2, t, N);
    k_aggregate<<<gAgg, 128>>>(t, b2, h, N, 1);
    // layer 3 -> d_out (first copy)
    float* out = (float*)d_out;
    k_gemm128<<<gGemm, 256, smem>>>(h, W3, t, N);
    k_aggregate<<<gAgg, 128>>>(t, b3, out, N, 0);

    // reference returns (h, h): duplicate if output holds both
    int half = N * FDIM;
    if (out_size >= 2 * half)
        k_dup<<<(half + 255) / 256, 256>>>(out, out + half, half);
}

// round 3
// speedup vs baseline: 1.8849x; 1.8849x over previous
#include <cuda_runtime.h>
#include <cstdint>

// ---------------- problem constants ----------------
#define NN     50000
#define FDIM   128
#define EMAX   600000

// ---------------- device scratch ----------------
__device__ float g_t[(size_t)NN * FDIM];     // GEMM output (pre-aggregation)
__device__ float g_h[(size_t)NN * FDIM];     // layer activations
__device__ int   g_cnt[NN];
__device__ int   g_cnt2[NN];
__device__ int   g_rowptr[NN + 1];
__device__ int   g_bsums[64];
__device__ float g_dinv[NN];
__device__ int   g_esrc[EMAX];
__device__ float g_enorm[EMAX];

// ---------------- setup kernels ----------------
__global__ void k_zero_counts(int n) {
    int i = blockIdx.x * blockDim.x + threadIdx.x;
    if (i < n) { g_cnt[i] = 0; g_cnt2[i] = 0; }
}

__global__ void k_count(const int* __restrict__ ei, int E) {
    int e = blockIdx.x * blockDim.x + threadIdx.x;
    if (e < E) atomicAdd(&g_cnt[ei[E + e]], 1);   // dst = row 1
}

// exclusive scan (block-level) + fused dinv
__global__ void k_scan1(int n) {
    __shared__ int s[1024];
    int i = blockIdx.x * 1024 + threadIdx.x;
    int v = (i < n) ? g_cnt[i] : 0;
    if (i < n) g_dinv[i] = rsqrtf((float)(v + 1));   // +1 self loop
    s[threadIdx.x] = v;
    __syncthreads();
    for (int off = 1; off < 1024; off <<= 1) {
        int t = (threadIdx.x >= off) ? s[threadIdx.x - off] : 0;
        __syncthreads();
        s[threadIdx.x] += t;
        __syncthreads();
    }
    if (i < n) g_rowptr[i] = s[threadIdx.x] - v;
    if (threadIdx.x == 1023) g_bsums[blockIdx.x] = s[1023];
}

__global__ void k_scan2(int nb) {
    int run = 0;
    for (int i = 0; i < nb; i++) { int v = g_bsums[i]; g_bsums[i] = run; run += v; }
}

__global__ void k_scan3(int n, int E) {
    int i = blockIdx.x * 1024 + threadIdx.x;
    if (i < n) g_rowptr[i] += g_bsums[blockIdx.x];
    if (i == 0) g_rowptr[n] = E;
}

__global__ void k_scatter(const int* __restrict__ ei, int E) {
    int e = blockIdx.x * blockDim.x + threadIdx.x;
    if (e >= E) return;
    int s = ei[e];
    int d = ei[E + e];
    int pos = g_rowptr[d] + atomicAdd(&g_cnt2[d], 1);
    g_esrc[pos]  = s;
    g_enorm[pos] = g_dinv[s] * g_dinv[d];
}

// ---------------- tf32 mma.sync GEMM ----------------
// C[row0:+128, 0:128] = A[rows,128] @ W[128,128]
// 256 threads = 8 warps; warp (wrow,wcol) owns 32x64; m16n8k8 tf32 HMMA.
// A: plain smem, pitch 132 floats (fragment gather is bank-conflict-free).
// B: lane-packed permuted smem (one lds.v2 per fragment).

#define APITCH 132
#define AP_FLOATS (128 * APITCH)                 // 16896 floats
#define SMEM_GEMM ((AP_FLOATS + 16384) * 4)      // + 16384 floats for Bs

__device__ __forceinline__ uint32_t cvt_tf32(float f) {
    uint32_t r; asm("cvt.rna.tf32.f32 %0, %1;" : "=r"(r) : "f"(f)); return r;
}

__device__ __forceinline__ void mma_tf32(float* c, const uint32_t* a, const uint32_t* b) {
    asm volatile(
        "mma.sync.aligned.m16n8k8.row.col.f32.tf32.tf32.f32 "
        "{%0,%1,%2,%3}, {%4,%5,%6,%7}, {%8,%9}, {%0,%1,%2,%3};"
        : "+f"(c[0]), "+f"(c[1]), "+f"(c[2]), "+f"(c[3])
        : "r"(a[0]), "r"(a[1]), "r"(a[2]), "r"(a[3]), "r"(b[0]), "r"(b[1]));
}

__global__ __launch_bounds__(256) void k_gemm_mma(const float* __restrict__ A,
                                                  const float* __restrict__ W,
                                                  float* __restrict__ C, int nrows) {
    extern __shared__ float sm[];
    float* Ap = sm;                        // [128][132] plain (tf32 bits)
    uint32_t* Apu = (uint32_t*)Ap;
    uint32_t* Bs = (uint32_t*)(sm + AP_FLOATS);   // 8192 slots x 2

    const int tid  = threadIdx.x;
    const int lane = tid & 31;
    const int wid  = tid >> 5;
    const int row0 = blockIdx.x * 128;

    // ---- phase 0: W -> Ap (plain, tf32-rounded), coalesced
#pragma unroll
    for (int i = 0; i < 16; i++) {
        int idx = i * 256 + tid;           // 4096 float4s
        int k  = idx >> 5;
        int n4 = idx & 31;
        float4 v = ((const float4*)(W + (size_t)k * 128))[n4];
        uint32_t* p = Apu + k * APITCH + n4 * 4;
        p[0] = cvt_tf32(v.x); p[1] = cvt_tf32(v.y);
        p[2] = cvt_tf32(v.z); p[3] = cvt_tf32(v.w);
    }
    __syncthreads();

    // ---- phase 1: permute W(plain) -> Bs (lane-packed fragment layout)
    // slot = (nt*16 + kt)*32 + lane ; values b0=W[kt*8+tg][nt*8+g], b1=+4 in k
    {
        int g = lane >> 2, tg = lane & 3;
#pragma unroll
        for (int i = 0; i < 32; i++) {
            int slot  = i * 256 + tid;     // 8192 slots
            int group = slot >> 5;         // nt*16 + kt
            int nt = group >> 4, kt = group & 15;
            uint32_t b0 = Apu[(kt * 8 + tg) * APITCH + nt * 8 + g];
            uint32_t b1 = Apu[(kt * 8 + tg + 4) * APITCH + nt * 8 + g];
            Bs[slot * 2]     = b0;
            Bs[slot * 2 + 1] = b1;
        }
    }
    __syncthreads();

    // ---- phase 2: A tile -> Ap (plain, tf32-rounded), coalesced + guarded
#pragma unroll
    for (int i = 0; i < 16; i++) {
        int idx = i * 256 + tid;
        int r  = idx >> 5;
        int k4 = idx & 31;
        float4 v = make_float4(0.f, 0.f, 0.f, 0.f);
        if (row0 + r < nrows)
            v = ((const float4*)(A + (size_t)(row0 + r) * 128))[k4];
        uint32_t* p = Apu + r * APITCH + k4 * 4;
        p[0] = cvt_tf32(v.x); p[1] = cvt_tf32(v.y);
        p[2] = cvt_tf32(v.z); p[3] = cvt_tf32(v.w);
    }
    __syncthreads();

    // ---- mainloop
    const int wrow = wid >> 1;             // 0..3  (32-row band)
    const int wcol = wid & 1;              // 0..1  (64-col band)
    const int g = lane >> 2, tg = lane & 3;

    float acc[2][8][4];
#pragma unroll
    for (int i = 0; i < 2; i++)
#pragma unroll
        for (int j = 0; j < 8; j++)
#pragma unroll
            for (int q = 0; q < 4; q++) acc[i][j][q] = 0.f;

#pragma unroll
    for (int kt = 0; kt < 16; kt++) {
        uint32_t af[2][4];
#pragma unroll
        for (int i = 0; i < 2; i++) {
            int r = wrow * 32 + i * 16 + g;
            int c = kt * 8 + tg;
            af[i][0] = Apu[r * APITCH + c];
            af[i][1] = Apu[(r + 8) * APITCH + c];
            af[i][2] = Apu[r * APITCH + c + 4];
            af[i][3] = Apu[(r + 8) * APITCH + c + 4];
        }
        uint32_t bf[8][2];
#pragma unroll
        for (int j = 0; j < 8; j++) {
            int nt = wcol * 8 + j;
            uint2 bv = *(const uint2*)&Bs[((nt * 16 + kt) * 32 + lane) * 2];
            bf[j][0] = bv.x; bf[j][1] = bv.y;
        }
#pragma unroll
        for (int i = 0; i < 2; i++)
#pragma unroll
            for (int j = 0; j < 8; j++)
                mma_tf32(acc[i][j], af[i], bf[j]);
    }

    // ---- epilogue: direct v2 stores
#pragma unroll
    for (int i = 0; i < 2; i++) {
        int r = row0 + wrow * 32 + i * 16 + g;
#pragma unroll
        for (int j = 0; j < 8; j++) {
            int col = wcol * 64 + j * 8 + tg * 2;
            if (r < nrows)
                *(float2*)(C + (size_t)r * 128 + col) =
                    make_float2(acc[i][j][0], acc[i][j][1]);
            if (r + 8 < nrows)
                *(float2*)(C + (size_t)(r + 8) * 128 + col) =
                    make_float2(acc[i][j][2], acc[i][j][3]);
        }
    }
}

// ---------------- aggregation ----------------
__global__ __launch_bounds__(128) void k_aggregate(const float* __restrict__ H,
                                                   const float* __restrict__ bias,
                                                   float* __restrict__ out,
                                                   float* __restrict__ out2,
                                                   int n, int relu) {
    int warp = threadIdx.x >> 5;
    int lane = threadIdx.x & 31;
    int node = blockIdx.x * 4 + warp;
    if (node >= n) return;

    float di = g_dinv[node];
    float di2 = di * di;
    float4 self = *(const float4*)(H + (size_t)node * 128 + lane * 4);
    float4 a0 = make_float4(self.x * di2, self.y * di2, self.z * di2, self.w * di2);
    float4 a1 = make_float4(0.f, 0.f, 0.f, 0.f);

    int e0 = g_rowptr[node], e1 = g_rowptr[node + 1];
    int e = e0;
    for (; e + 1 < e1; e += 2) {
        int   s0 = g_esrc[e],  s1 = g_esrc[e + 1];
        float m0 = g_enorm[e], m1 = g_enorm[e + 1];
        float4 h0 = *(const float4*)(H + (size_t)s0 * 128 + lane * 4);
        float4 h1 = *(const float4*)(H + (size_t)s1 * 128 + lane * 4);
        a0.x = fmaf(h0.x, m0, a0.x); a0.y = fmaf(h0.y, m0, a0.y);
        a0.z = fmaf(h0.z, m0, a0.z); a0.w = fmaf(h0.w, m0, a0.w);
        a1.x = fmaf(h1.x, m1, a1.x); a1.y = fmaf(h1.y, m1, a1.y);
        a1.z = fmaf(h1.z, m1, a1.z); a1.w = fmaf(h1.w, m1, a1.w);
    }
    if (e < e1) {
        int   s0 = g_esrc[e];
        float m0 = g_enorm[e];
        float4 h0 = *(const float4*)(H + (size_t)s0 * 128 + lane * 4);
        a0.x = fmaf(h0.x, m0, a0.x); a0.y = fmaf(h0.y, m0, a0.y);
        a0.z = fmaf(h0.z, m0, a0.z); a0.w = fmaf(h0.w, m0, a0.w);
    }

    float4 b = *(const float4*)(bias + lane * 4);
    float4 o = make_float4(a0.x + a1.x + b.x, a0.y + a1.y + b.y,
                           a0.z + a1.z + b.z, a0.w + a1.w + b.w);
    if (relu) {
        o.x = fmaxf(o.x, 0.f); o.y = fmaxf(o.y, 0.f);
        o.z = fmaxf(o.z, 0.f); o.w = fmaxf(o.w, 0.f);
    }
    size_t off = (size_t)node * 128 + lane * 4;
    *(float4*)(out + off) = o;
    if (out2) *(float4*)(out2 + off) = o;
}

// ---------------- launch ----------------
extern "C" void kernel_launch(void* const* d_in, const int* in_sizes, int n_in,
                              void* d_out, int out_size) {
    const float* x  = (const float*)d_in[0];
    const int*   ei = (const int*)d_in[1];
    const float* W1 = (const float*)d_in[2];
    const float* b1 = (const float*)d_in[3];
    const float* W2 = (const float*)d_in[4];
    const float* b2 = (const float*)d_in[5];
    const float* W3 = (const float*)d_in[6];
    const float* b3 = (const float*)d_in[7];

    int N = in_sizes[0] / FDIM;
    if (N > NN) N = NN;
    int E = in_sizes[1] / 2;
    if (E > EMAX) E = EMAX;

    static float* t = nullptr;
    static float* h = nullptr;
    static bool inited = false;
    if (!inited) {
        cudaGetSymbolAddress((void**)&t, g_t);
        cudaGetSymbolAddress((void**)&h, g_h);
        cudaFuncSetAttribute(k_gemm_mma, cudaFuncAttributeMaxDynamicSharedMemorySize,
                             SMEM_GEMM);
        inited = true;
    }

    const int nScan = (N + 1023) / 1024;

    // CSR + normalization build
    k_zero_counts<<<(N + 255) / 256, 256>>>(N);
    k_count<<<(E + 255) / 256, 256>>>(ei, E);
    k_scan1<<<nScan, 1024>>>(N);
    k_scan2<<<1, 1>>>(nScan);
    k_scan3<<<nScan, 1024>>>(N, E);
    k_scatter<<<(E + 255) / 256, 256>>>(ei, E);

    const int gGemm = (N + 127) / 128;
    const int gAgg  = (N + 3) / 4;
    float* out = (float*)d_out;
    int half = N * FDIM;
    float* out2 = (out_size >= 2 * half) ? out + half : nullptr;

    k_gemm_mma<<<gGemm, 256, SMEM_GEMM>>>(x, W1, t, N);
    k_aggregate<<<gAgg, 128>>>(t, b1, h, nullptr, N, 1);
    k_gemm_mma<<<gGemm, 256, SMEM_GEMM>>>(h, W2, t, N);
    k_aggregate<<<gAgg, 128>>>(t, b2, h, nullptr, N, 1);
    k_gemm_mma<<<gGemm, 256, SMEM_GEMM>>>(h, W3, t, N);
    k_aggregate<<<gAgg, 128>>>(t, b3, out, out2, N, 0);
}